// round 15
// baseline (speedup 1.0000x reference)
#include <cuda_runtime.h>
#include <cuda_fp16.h>
#include <cuda_bf16.h>
#include <cstdint>

// Problem constants
#define T      8192
#define NF     128
#define CINP   128
#define LOG2E  1.4426950408889634f
#define QSCALE 0.08838834764831845f  // 1/sqrt(128)
#define NSPLIT_MAX 8

// Attention tiling
#define BM 128
#define BN 64
#define NKT 16
#define KSTB 288
#define VSTB 160
#define PSTB 160
#define QSTB 288
#define NCTA_ATTN 288   // exact working-CTA count: sum_g 8*(g+1), g=0..7

// smem layout (bytes) — single KV buffer, resident Q  => 2 CTAs/SM
#define K_TILE  (64 * KSTB)          // 18432
#define V_TILE  (128 * VSTB)         // 20480
#define KV_BUF  (K_TILE + V_TILE)    // 38912
#define PS_OFF  KV_BUF
#define PS_SIZE (8 * 16 * PSTB)      // 20480
#define QS_OFF  (PS_OFF + PS_SIZE)
#define QS_SIZE (128 * QSTB)         // 36864
#define ATTN_SMEM (QS_OFF + QS_SIZE) // 96256

// Scratch.  Packed fragment-order operand tensors.
__device__ __nv_bfloat16 g_Qh[T * NF];   // [row][packc16(d)], scaled QSCALE*log2e
__device__ __nv_bfloat16 g_Kh[T * NF];   // [key][packc16(d)]
__device__ __half        g_Vh[NF * T];   // [d][packc16(key)]
__device__ float g_O[NSPLIT_MAX * T * NF];
__device__ float g_L[NSPLIT_MAX * T];

__device__ __forceinline__ float neg_inf() { return __int_as_float(0xff800000u); }

__device__ __forceinline__ uint32_t f2tf32(float f) {
  uint32_t u;
  asm("cvt.rna.tf32.f32 %0, %1;" : "=r"(u) : "f"(f));
  return u;
}
__device__ __forceinline__ float tf32f(float f) {
  return __uint_as_float(f2tf32(f));
}

// pack two f32 -> f16x2, then exp2 in fp16x2.
// ex2.approx.f16 maps -inf -> +0 (PTX spec), so masked logits vanish exactly.
__device__ __forceinline__ uint32_t exp2_f16x2(float a, float b) {
  uint32_t h, r;
  asm("cvt.rn.f16x2.f32 %0, %1, %2;" : "=r"(h) : "f"(b), "f"(a));
  asm("ex2.approx.f16x2 %0, %1;" : "=r"(r) : "r"(h));
  return r;
}

// fragment-order permutation within each 16-group; keeps (2a, 2a+1) adjacent
__device__ __forceinline__ int packc16(int c) {
  int u = c & 7, pr = (c >> 3) & 1;
  return (c & ~15) | (((u >> 1) << 2) | (u & 1) | (pr << 1));
}

__device__ __forceinline__ void mma_tf32(float* d, const uint32_t* a,
                                         const uint32_t* b) {
  asm volatile(
      "mma.sync.aligned.m16n8k8.row.col.f32.tf32.tf32.f32 "
      "{%0,%1,%2,%3}, {%4,%5,%6,%7}, {%8,%9}, {%0,%1,%2,%3};\n"
      : "+f"(d[0]), "+f"(d[1]), "+f"(d[2]), "+f"(d[3])
      : "r"(a[0]), "r"(a[1]), "r"(a[2]), "r"(a[3]), "r"(b[0]), "r"(b[1]));
}
__device__ __forceinline__ void mma_bf16(float* d, const uint32_t* a,
                                         const uint32_t* b) {
  asm volatile(
      "mma.sync.aligned.m16n8k16.row.col.f32.bf16.bf16.f32 "
      "{%0,%1,%2,%3}, {%4,%5,%6,%7}, {%8,%9}, {%0,%1,%2,%3};\n"
      : "+f"(d[0]), "+f"(d[1]), "+f"(d[2]), "+f"(d[3])
      : "r"(a[0]), "r"(a[1]), "r"(a[2]), "r"(a[3]), "r"(b[0]), "r"(b[1]));
}
__device__ __forceinline__ void mma_f16(float* d, const uint32_t* a,
                                        const uint32_t* b) {
  asm volatile(
      "mma.sync.aligned.m16n8k16.row.col.f32.f16.f16.f32 "
      "{%0,%1,%2,%3}, {%4,%5,%6,%7}, {%8,%9}, {%0,%1,%2,%3};\n"
      : "+f"(d[0]), "+f"(d[1]), "+f"(d[2]), "+f"(d[3])
      : "r"(a[0]), "r"(a[1]), "r"(a[2]), "r"(a[3]), "r"(b[0]), "r"(b[1]));
}

__device__ __forceinline__ uint32_t smem_u32(const void* p) {
  uint32_t a;
  asm("{ .reg .u64 t; cvta.to.shared.u64 t, %1; cvt.u32.u64 %0, t; }"
      : "=r"(a) : "l"(p));
  return a;
}
__device__ __forceinline__ void cp16(uint32_t daddr, const void* src) {
  asm volatile("cp.async.cg.shared.global [%0], [%1], 16;"
               :: "r"(daddr), "l"(src));
}
#define CP_COMMIT() asm volatile("cp.async.commit_group;" ::: "memory")
#define CP_WAIT1()  asm volatile("cp.async.wait_group 1;" ::: "memory")
#define CP_WAIT0()  asm volatile("cp.async.wait_group 0;" ::: "memory")

// ---------------------------------------------------------------------------
// Kernel 1: QKV projection (round-12 config, unchanged: grid (64,6), 2 CTAs/SM).
// ---------------------------------------------------------------------------
#define XST 132
#define WST2 136
__global__ void __launch_bounds__(256, 2) proj_kernel(
    const float* __restrict__ x, const float* __restrict__ W,
    const float* __restrict__ bias, const int* __restrict__ npadd_p) {
  extern __shared__ float sm[];
  float* xs = sm;                 // [128][XST] raw fp32 (reused as staging)
  float* ws = sm + 128 * XST;     // packed W: [64][WST2] tf32-rounded

  const int tid = threadIdx.x;
  const int lane = tid & 31;
  const int w = tid >> 5;
  const int tq = lane >> 2;
  const int tr = lane & 3;
  const int row0 = blockIdx.x * 128;
  const int col0 = blockIdx.y * 64;
  const uint32_t sbx = smem_u32(xs);

  // x: async copy straight into smem (overlaps with W staging below)
#pragma unroll
  for (int it = 0; it < 16; ++it) {
    int idx = tid + it * 256;
    int r = idx >> 5, seg = idx & 31;
    cp16(sbx + (r * XST + seg * 4) * 4, &x[(row0 + r) * CINP + seg * 4]);
  }
  CP_COMMIT();

  // W: permuted k-pair staging with rna rounding (unbiased)
#pragma unroll
  for (int it = 0; it < 8; ++it) {
    int idx = tid + it * 256;
    int k = idx >> 4, n4 = idx & 15;
    float4 v = *(const float4*)&W[k * (3 * NF) + col0 + n4 * 4];
    int kp = ((k & 3) + ((k >> 3) << 2)) * WST2 + ((k >> 2) & 1);
    ws[kp + (n4 * 4 + 0) * 2] = tf32f(v.x);
    ws[kp + (n4 * 4 + 1) * 2] = tf32f(v.y);
    ws[kp + (n4 * 4 + 2) * 2] = tf32f(v.z);
    ws[kp + (n4 * 4 + 3) * 2] = tf32f(v.w);
  }

  // hoist epilogue loads: bias pairs + npadd (latency hidden under mma loop)
  float2 bb2[8];
#pragma unroll
  for (int nt = 0; nt < 8; ++nt)
    bb2[nt] = *(const float2*)&bias[col0 + nt * 8 + 2 * tr];
  const int npadd = *npadd_p;

  CP_WAIT0();
  __syncthreads();

  float s[8][4];
#pragma unroll
  for (int n = 0; n < 8; ++n)
#pragma unroll
    for (int i = 0; i < 4; ++i) s[n][i] = 0.0f;

  const float* x0 = &xs[(16 * w + tq) * XST];
  const float* x1 = &xs[(16 * w + tq + 8) * XST];

#pragma unroll
  for (int kk = 0; kk < 16; ++kk) {
    uint32_t ah[4];
    ah[0] = f2tf32(x0[kk * 8 + tr]);       // rna: unbiased tf32
    ah[1] = f2tf32(x1[kk * 8 + tr]);
    ah[2] = f2tf32(x0[kk * 8 + tr + 4]);
    ah[3] = f2tf32(x1[kk * 8 + tr + 4]);
    const float* wrow = &ws[(kk * 4 + tr) * WST2];
#pragma unroll
    for (int nt = 0; nt < 8; ++nt) {
      float2 wv = *(const float2*)&wrow[(nt * 8 + tq) * 2];
      uint32_t bbx[2] = {__float_as_uint(wv.x), __float_as_uint(wv.y)};
      mma_tf32(s[nt], ah, bbx);
    }
  }

  const int sec = blockIdx.y >> 1;          // 0:q 1:k 2:v
  const int wcb = (blockIdx.y & 1) * 64;
  const int lr0 = 16 * w + tq;
  const int lr1 = lr0 + 8;
  const float qmul = QSCALE * LOG2E;

  __syncthreads();
  char* stg = (char*)sm;

  if (sec < 2) {
    const float scale = (sec == 0) ? qmul : 1.0f;
#pragma unroll
    for (int nt = 0; nt < 8; ++nt) {
      int c0 = nt * 8 + 2 * tr;
      int pp = packc16(c0) * 2;
      float b0 = bb2[nt].x, b1 = bb2[nt].y;
      __nv_bfloat162 v0, v1;
      v0.x = __float2bfloat16_rn((s[nt][0] + b0) * scale);
      v0.y = __float2bfloat16_rn((s[nt][1] + b1) * scale);
      v1.x = __float2bfloat16_rn((s[nt][2] + b0) * scale);
      v1.y = __float2bfloat16_rn((s[nt][3] + b1) * scale);
      *(__nv_bfloat162*)(stg + lr0 * 144 + pp) = v0;
      *(__nv_bfloat162*)(stg + lr1 * 144 + pp) = v1;
    }
  } else {
    const bool z0 = (row0 + lr0) < npadd;
    const bool z1 = (row0 + lr1) < npadd;
    const int pk0 = packc16(lr0) * 2, pk1 = packc16(lr1) * 2;
#pragma unroll
    for (int nt = 0; nt < 8; ++nt) {
      int c0 = nt * 8 + 2 * tr, c1 = c0 + 1;
      float b0 = bb2[nt].x, b1 = bb2[nt].y;
      *(__half*)(stg + c0 * 272 + pk0) = __float2half_rn(z0 ? 0.0f : s[nt][0] + b0);
      *(__half*)(stg + c1 * 272 + pk0) = __float2half_rn(z0 ? 0.0f : s[nt][1] + b1);
      *(__half*)(stg + c0 * 272 + pk1) = __float2half_rn(z1 ? 0.0f : s[nt][2] + b0);
      *(__half*)(stg + c1 * 272 + pk1) = __float2half_rn(z1 ? 0.0f : s[nt][3] + b1);
    }
  }
  __syncthreads();

  if (sec < 2) {
    char* gd = (char*)((sec == 0) ? g_Qh : g_Kh);
#pragma unroll
    for (int it = 0; it < 4; ++it) {
      int idx = tid + it * 256;
      int r = idx >> 3, seg = idx & 7;
      *(float4*)(gd + (size_t)(row0 + r) * 256 + wcb * 2 + seg * 16) =
          *(const float4*)(stg + r * 144 + seg * 16);
    }
  } else {
    char* gd = (char*)g_Vh;
#pragma unroll
    for (int it = 0; it < 4; ++it) {
      int idx = tid + it * 256;
      int d = idx >> 4, seg = idx & 15;
      *(float4*)(gd + ((size_t)(wcb + d) * T + row0) * 2 + seg * 16) =
          *(const float4*)(stg + d * 272 + seg * 16);
    }
  }
}

// ---------------------------------------------------------------------------
// Kernel 2: flash attention.  Even-split chunks (sizes within 1 tile of each
// other per qtile) + complementary-pair launch order: CTA b and b+148 share
// an SM, so rank = b<148 ? b : 435-b pairs a heavy chunk with a light one.
// ---------------------------------------------------------------------------
__global__ void __launch_bounds__(256, 2) attn_kernel(const int* __restrict__ npadd_p,
                                                      float* __restrict__ out) {
  extern __shared__ char smc[];

  const int tid = threadIdx.x;
  const int lane = tid & 31;
  const int w = tid >> 5;
  const int tq = lane >> 2;
  const int tr = lane & 3;

  // complementary-pair order: rank 0 = heaviest chunk
  const int bx = blockIdx.x;
  const int rank = (bx < 148) ? bx : (435 - bx);
  const int bid = (NCTA_ATTN - 1) - rank;        // internal id: ascending size
  // bid -> (qt, ch): group g = qt>>3 has 8 qtiles x (g+1) chunks.
  int g = 0;
  while (4 * (g + 1) * (g + 2) <= bid) ++g;
  const int idx0 = bid - 4 * g * (g + 1);
  const int qi = idx0 / (g + 1);
  const int ch = idx0 - qi * (g + 1);
  const int qt = 8 * g + qi;
  const int nch = g + 1;

  const int kcount = 2 * (qt + 1);
  const int k0 = (ch * kcount) / nch;            // even-split chunks
  const int k1 = ((ch + 1) * kcount) / nch;
  const int npadd = *npadd_p;
  const int qrow0 = qt * BM;

  const uint32_t sb = smem_u32(smc);

  // ---- prologue: group 1 = Q + K(0); group 2 = V(0) ----
  {
    const char* qsrc = (const char*)g_Qh + (size_t)qrow0 * (NF * 2);
#pragma unroll
    for (int it = 0; it < 8; ++it) {
      int idx = tid + it * 256;
      int r = idx >> 4, seg = idx & 15;
      cp16(sb + QS_OFF + r * QSTB + seg * 16, qsrc + r * (NF * 2) + seg * 16);
    }
    const int kbase = k0 * BN;
    const char* ksrc = (const char*)g_Kh + (size_t)kbase * (NF * 2);
#pragma unroll
    for (int it = 0; it < 4; ++it) {
      int idx = tid + it * 256;
      int r = idx >> 4, seg = idx & 15;
      cp16(sb + r * KSTB + seg * 16, ksrc + r * (NF * 2) + seg * 16);
    }
    CP_COMMIT();                           // group: Q + K(0)
    const char* vsrc = (const char*)g_Vh + (size_t)kbase * 2;
#pragma unroll
    for (int it = 0; it < 4; ++it) {
      int idx = tid + it * 256;
      int r = idx >> 3, seg = idx & 7;
      cp16(sb + K_TILE + r * VSTB + seg * 16, vsrc + (size_t)r * (T * 2) + seg * 16);
    }
    CP_COMMIT();                           // group: V(0)
    CP_WAIT1();                            // Q + K(0) complete; V(0) in flight
  }
  __syncthreads();

  const int r0g = qrow0 + 16 * w + tq;
  const int r1g = r0g + 8;
  float o[16][4];
#pragma unroll
  for (int n = 0; n < 16; ++n)
#pragma unroll
    for (int i = 0; i < 4; ++i) o[n][i] = 0.0f;
  float oS[4] = {0.0f, 0.0f, 0.0f, 0.0f};   // row sums via ones-mma
  const uint32_t ones2[2] = {0x3C003C00u, 0x3C003C00u};

  char* pw = smc + PS_OFF + w * 16 * PSTB;
  const char* q0p = smc + QS_OFF + (16 * w + tq) * QSTB + tr * 8;
  const char* Ks = smc;
  const char* Vs = smc + K_TILE;

  for (int kt = k0; kt < k1; ++kt) {
    const int kbase = kt * BN;

    // ---- S = Q @ K^T ----
    float s[8][4];
#pragma unroll
    for (int n = 0; n < 8; ++n)
#pragma unroll
      for (int i = 0; i < 4; ++i) s[n][i] = 0.0f;

#pragma unroll
    for (int kk = 0; kk < 8; ++kk) {
      uint2 l0 = *(const uint2*)(q0p + kk * 32);
      uint2 l1 = *(const uint2*)(q0p + 8 * QSTB + kk * 32);
      uint32_t qa[4] = {l0.x, l1.x, l0.y, l1.y};
#pragma unroll
      for (int nt = 0; nt < 8; ++nt) {
        uint2 bb = *(const uint2*)(Ks + (nt * 8 + tq) * KSTB + kk * 32 + tr * 8);
        mma_bf16(s[nt], qa, (const uint32_t*)&bb);
      }
    }
    __syncthreads();                       // all warps done reading Ks

    // ---- prefetch K(t+1) ----
    if (kt + 1 < k1) {
      const char* ksrc = (const char*)g_Kh + (size_t)(kt + 1) * BN * (NF * 2);
#pragma unroll
      for (int it = 0; it < 4; ++it) {
        int idx = tid + it * 256;
        int r = idx >> 4, seg = idx & 15;
        cp16(sb + r * KSTB + seg * 16, ksrc + r * (NF * 2) + seg * 16);
      }
    }
    CP_COMMIT();                           // K group

    // ---- mask ----
    const bool needmask = (kbase + BN > qrow0) || (kbase < npadd) || (qrow0 < npadd);
    if (needmask) {
#pragma unroll
      for (int nt = 0; nt < 8; ++nt) {
        int j0 = kbase + nt * 8 + 2 * tr;
        int j1 = j0 + 1;
        if (j0 > r0g || j0 < npadd || r0g < npadd) s[nt][0] = neg_inf();
        if (j1 > r0g || j1 < npadd || r0g < npadd) s[nt][1] = neg_inf();
        if (j0 > r1g || j0 < npadd || r1g < npadd) s[nt][2] = neg_inf();
        if (j1 > r1g || j1 < npadd || r1g < npadd) s[nt][3] = neg_inf();
      }
    }

    // ---- P = exp2(S) in fp16x2 (no max subtraction needed) ----
#pragma unroll
    for (int nth = 0; nth < 4; ++nth) {
      int nt = 2 * nth;
      uint2 st0, st1;
      st0.x = exp2_f16x2(s[nt][0], s[nt][1]);
      st0.y = exp2_f16x2(s[nt + 1][0], s[nt + 1][1]);
      st1.x = exp2_f16x2(s[nt][2], s[nt][3]);
      st1.y = exp2_f16x2(s[nt + 1][2], s[nt + 1][3]);
      int off = nth * 32 + tr * 8;
      *(uint2*)(pw + tq * PSTB + off) = st0;
      *(uint2*)(pw + (tq + 8) * PSTB + off) = st1;
    }

    CP_WAIT1();                            // V(t) complete (older than K(t+1))
    __syncthreads();                       // V + P visible

    // ---- O += P @ V ; row sums += P @ ones ----
#pragma unroll
    for (int ktk = 0; ktk < 4; ++ktk) {
      uint2 p0 = *(const uint2*)(pw + tq * PSTB + ktk * 32 + tr * 8);
      uint2 p1 = *(const uint2*)(pw + (tq + 8) * PSTB + ktk * 32 + tr * 8);
      uint32_t pa[4] = {p0.x, p1.x, p0.y, p1.y};
#pragma unroll
      for (int nt2 = 0; nt2 < 16; ++nt2) {
        uint2 bb = *(const uint2*)(Vs + (nt2 * 8 + tq) * VSTB + ktk * 32 + tr * 8);
        mma_f16(o[nt2], pa, (const uint32_t*)&bb);
      }
      mma_f16(oS, pa, ones2);              // l accumulation on the tensor pipe
    }
    __syncthreads();                       // all warps done reading Vs

    // ---- prefetch V(t+1) ----
    if (kt + 1 < k1) {
      const char* vsrc = (const char*)g_Vh + (size_t)(kt + 1) * BN * 2;
#pragma unroll
      for (int it = 0; it < 4; ++it) {
        int idx = tid + it * 256;
        int r = idx >> 3, seg = idx & 7;
        cp16(sb + K_TILE + r * VSTB + seg * 16, vsrc + (size_t)r * (T * 2) + seg * 16);
      }
    }
    CP_COMMIT();                           // V group
    CP_WAIT1();                            // K(t+1) complete
    __syncthreads();                       // K visible
  }

  const float l0s = oS[0];
  const float l1s = oS[2];

  // ---- epilogue ----
  if (nch == 1) {
    float rn0 = (l0s > 0.0f) ? (1.0f / l0s) : 0.0f;
    float rn1 = (l1s > 0.0f) ? (1.0f / l1s) : 0.0f;
    float* ob0 = &out[(size_t)r0g * NF];
    float* ob1 = &out[(size_t)r1g * NF];
#pragma unroll
    for (int nt2 = 0; nt2 < 16; ++nt2) {
      int c = nt2 * 8 + 2 * tr;
      *(float2*)&ob0[c] = make_float2(o[nt2][0] * rn0, o[nt2][1] * rn0);
      *(float2*)&ob1[c] = make_float2(o[nt2][2] * rn1, o[nt2][3] * rn1);
    }
  } else {
    float* ob0 = &g_O[((size_t)ch * T + r0g) * NF];
    float* ob1 = &g_O[((size_t)ch * T + r1g) * NF];
#pragma unroll
    for (int nt2 = 0; nt2 < 16; ++nt2) {
      int c = nt2 * 8 + 2 * tr;
      *(float2*)&ob0[c] = make_float2(o[nt2][0], o[nt2][1]);
      *(float2*)&ob1[c] = make_float2(o[nt2][2], o[nt2][3]);
    }
    if (tr == 0) {
      g_L[ch * T + r0g] = l0s; g_L[ch * T + r1g] = l1s;
    }
  }
}

// ---------------------------------------------------------------------------
// Kernel 3: combine split partials (plain sums) — rows >= 1024.
// ---------------------------------------------------------------------------
__global__ void __launch_bounds__(256) combine_kernel(float* __restrict__ out) {
  const int tid = threadIdx.x;
  const int t = 1024 + blockIdx.x * 2 + (tid >> 7);
  const int c = tid & 127;
  const int qt = t >> 7;
  const int nch = (qt >> 3) + 1;

  float den = 0.0f, num = 0.0f;
  for (int s = 0; s < nch; ++s) {
    den += g_L[s * T + t];
    num += g_O[((size_t)s * T + t) * NF + c];
  }
  out[t * NF + c] = (den > 0.0f) ? (num / den) : 0.0f;
}

// ---------------------------------------------------------------------------
extern "C" void kernel_launch(void* const* d_in, const int* in_sizes, int n_in,
                              void* d_out, int out_size) {
  const float* x = (const float*)d_in[0];
  const float* W = (const float*)d_in[1];
  const float* b = (const float*)d_in[2];
  const int* npadd = (const int*)d_in[3];
  float* out = (float*)d_out;

  constexpr int PROJ_SMEM = (128 * XST + 64 * WST2) * (int)sizeof(float);  // 100KB
  cudaFuncSetAttribute(proj_kernel, cudaFuncAttributeMaxDynamicSharedMemorySize, PROJ_SMEM);
  cudaFuncSetAttribute(attn_kernel, cudaFuncAttributeMaxDynamicSharedMemorySize, ATTN_SMEM);

  proj_kernel<<<dim3(64, 6), 256, PROJ_SMEM>>>(x, W, b, npadd);
  attn_kernel<<<NCTA_ATTN, 256, ATTN_SMEM>>>(npadd, out);
  combine_kernel<<<(T - 1024) / 2, 256>>>(out);
}

// round 16
// speedup vs baseline: 1.0208x; 1.0208x over previous
#include <cuda_runtime.h>
#include <cuda_fp16.h>
#include <cuda_bf16.h>
#include <cstdint>

// Problem constants
#define T      8192
#define NF     128
#define CINP   128
#define LOG2E  1.4426950408889634f
#define QSCALE 0.08838834764831845f  // 1/sqrt(128)
#define NSPLIT_MAX 8

// Attention tiling
#define BM 128
#define BN 64
#define NKT 16
#define KSTB 288
#define VSTB 160
#define PSTB 160
#define QSTB 288
#define NCTA_ATTN 288   // exact working-CTA count: sum_g 8*(g+1), g=0..7

// smem layout (bytes) — single KV buffer, resident Q  => 2 CTAs/SM
#define K_TILE  (64 * KSTB)          // 18432
#define V_TILE  (128 * VSTB)         // 20480
#define KV_BUF  (K_TILE + V_TILE)    // 38912
#define PS_OFF  KV_BUF
#define PS_SIZE (8 * 16 * PSTB)      // 20480
#define QS_OFF  (PS_OFF + PS_SIZE)
#define QS_SIZE (128 * QSTB)         // 36864
#define ATTN_SMEM (QS_OFF + QS_SIZE) // 96256

// Scratch.  Packed fragment-order operand tensors.
__device__ __nv_bfloat16 g_Qh[T * NF];   // [row][packc16(d)], scaled QSCALE*log2e
__device__ __nv_bfloat16 g_Kh[T * NF];   // [key][packc16(d)]
__device__ __half        g_Vh[NF * T];   // [d][packc16(key)]
__device__ float g_O[NSPLIT_MAX * T * NF];
__device__ float g_L[NSPLIT_MAX * T];

__device__ __forceinline__ float neg_inf() { return __int_as_float(0xff800000u); }

__device__ __forceinline__ uint32_t f2tf32(float f) {
  uint32_t u;
  asm("cvt.rna.tf32.f32 %0, %1;" : "=r"(u) : "f"(f));
  return u;
}
__device__ __forceinline__ float tf32f(float f) {
  return __uint_as_float(f2tf32(f));
}

// pack two f32 -> f16x2, then exp2 in fp16x2.
// ex2.approx.f16 maps -inf -> +0 (PTX spec), so masked logits vanish exactly.
__device__ __forceinline__ uint32_t exp2_f16x2(float a, float b) {
  uint32_t h, r;
  asm("cvt.rn.f16x2.f32 %0, %1, %2;" : "=r"(h) : "f"(b), "f"(a));
  asm("ex2.approx.f16x2 %0, %1;" : "=r"(r) : "r"(h));
  return r;
}

// fragment-order permutation within each 16-group; keeps (2a, 2a+1) adjacent
__device__ __forceinline__ int packc16(int c) {
  int u = c & 7, pr = (c >> 3) & 1;
  return (c & ~15) | (((u >> 1) << 2) | (u & 1) | (pr << 1));
}

__device__ __forceinline__ void mma_tf32(float* d, const uint32_t* a,
                                         const uint32_t* b) {
  asm volatile(
      "mma.sync.aligned.m16n8k8.row.col.f32.tf32.tf32.f32 "
      "{%0,%1,%2,%3}, {%4,%5,%6,%7}, {%8,%9}, {%0,%1,%2,%3};\n"
      : "+f"(d[0]), "+f"(d[1]), "+f"(d[2]), "+f"(d[3])
      : "r"(a[0]), "r"(a[1]), "r"(a[2]), "r"(a[3]), "r"(b[0]), "r"(b[1]));
}
__device__ __forceinline__ void mma_bf16(float* d, const uint32_t* a,
                                         const uint32_t* b) {
  asm volatile(
      "mma.sync.aligned.m16n8k16.row.col.f32.bf16.bf16.f32 "
      "{%0,%1,%2,%3}, {%4,%5,%6,%7}, {%8,%9}, {%0,%1,%2,%3};\n"
      : "+f"(d[0]), "+f"(d[1]), "+f"(d[2]), "+f"(d[3])
      : "r"(a[0]), "r"(a[1]), "r"(a[2]), "r"(a[3]), "r"(b[0]), "r"(b[1]));
}
__device__ __forceinline__ void mma_f16(float* d, const uint32_t* a,
                                        const uint32_t* b) {
  asm volatile(
      "mma.sync.aligned.m16n8k16.row.col.f32.f16.f16.f32 "
      "{%0,%1,%2,%3}, {%4,%5,%6,%7}, {%8,%9}, {%0,%1,%2,%3};\n"
      : "+f"(d[0]), "+f"(d[1]), "+f"(d[2]), "+f"(d[3])
      : "r"(a[0]), "r"(a[1]), "r"(a[2]), "r"(a[3]), "r"(b[0]), "r"(b[1]));
}

__device__ __forceinline__ uint32_t smem_u32(const void* p) {
  uint32_t a;
  asm("{ .reg .u64 t; cvta.to.shared.u64 t, %1; cvt.u32.u64 %0, t; }"
      : "=r"(a) : "l"(p));
  return a;
}
__device__ __forceinline__ void cp16(uint32_t daddr, const void* src) {
  asm volatile("cp.async.cg.shared.global [%0], [%1], 16;"
               :: "r"(daddr), "l"(src));
}
#define CP_COMMIT() asm volatile("cp.async.commit_group;" ::: "memory")
#define CP_WAIT1()  asm volatile("cp.async.wait_group 1;" ::: "memory")
#define CP_WAIT0()  asm volatile("cp.async.wait_group 0;" ::: "memory")

// ---------------------------------------------------------------------------
// Kernel 1: QKV projection (round-12/14 config: grid (64,6), 2 CTAs/SM).
// x via cp.async (raw), rna-rounded at fragment extraction; W staged rna.
// ---------------------------------------------------------------------------
#define XST 132
#define WST2 136
__global__ void __launch_bounds__(256, 2) proj_kernel(
    const float* __restrict__ x, const float* __restrict__ W,
    const float* __restrict__ bias, const int* __restrict__ npadd_p) {
  extern __shared__ float sm[];
  float* xs = sm;                 // [128][XST] raw fp32 (reused as staging)
  float* ws = sm + 128 * XST;     // packed W: [64][WST2] tf32-rounded

  const int tid = threadIdx.x;
  const int lane = tid & 31;
  const int w = tid >> 5;
  const int tq = lane >> 2;
  const int tr = lane & 3;
  const int row0 = blockIdx.x * 128;
  const int col0 = blockIdx.y * 64;
  const uint32_t sbx = smem_u32(xs);

  // x: async copy straight into smem (overlaps with W staging below)
#pragma unroll
  for (int it = 0; it < 16; ++it) {
    int idx = tid + it * 256;
    int r = idx >> 5, seg = idx & 31;
    cp16(sbx + (r * XST + seg * 4) * 4, &x[(row0 + r) * CINP + seg * 4]);
  }
  CP_COMMIT();

  // W: permuted k-pair staging with rna rounding (unbiased)
#pragma unroll
  for (int it = 0; it < 8; ++it) {
    int idx = tid + it * 256;
    int k = idx >> 4, n4 = idx & 15;
    float4 v = *(const float4*)&W[k * (3 * NF) + col0 + n4 * 4];
    int kp = ((k & 3) + ((k >> 3) << 2)) * WST2 + ((k >> 2) & 1);
    ws[kp + (n4 * 4 + 0) * 2] = tf32f(v.x);
    ws[kp + (n4 * 4 + 1) * 2] = tf32f(v.y);
    ws[kp + (n4 * 4 + 2) * 2] = tf32f(v.z);
    ws[kp + (n4 * 4 + 3) * 2] = tf32f(v.w);
  }

  // hoist epilogue loads: bias pairs + npadd (latency hidden under mma loop)
  float2 bb2[8];
#pragma unroll
  for (int nt = 0; nt < 8; ++nt)
    bb2[nt] = *(const float2*)&bias[col0 + nt * 8 + 2 * tr];
  const int npadd = *npadd_p;

  CP_WAIT0();
  __syncthreads();

  float s[8][4];
#pragma unroll
  for (int n = 0; n < 8; ++n)
#pragma unroll
    for (int i = 0; i < 4; ++i) s[n][i] = 0.0f;

  const float* x0 = &xs[(16 * w + tq) * XST];
  const float* x1 = &xs[(16 * w + tq + 8) * XST];

#pragma unroll
  for (int kk = 0; kk < 16; ++kk) {
    uint32_t ah[4];
    ah[0] = f2tf32(x0[kk * 8 + tr]);       // rna: unbiased tf32
    ah[1] = f2tf32(x1[kk * 8 + tr]);
    ah[2] = f2tf32(x0[kk * 8 + tr + 4]);
    ah[3] = f2tf32(x1[kk * 8 + tr + 4]);
    const float* wrow = &ws[(kk * 4 + tr) * WST2];
#pragma unroll
    for (int nt = 0; nt < 8; ++nt) {
      float2 wv = *(const float2*)&wrow[(nt * 8 + tq) * 2];
      uint32_t bbx[2] = {__float_as_uint(wv.x), __float_as_uint(wv.y)};
      mma_tf32(s[nt], ah, bbx);
    }
  }

  const int sec = blockIdx.y >> 1;          // 0:q 1:k 2:v
  const int wcb = (blockIdx.y & 1) * 64;
  const int lr0 = 16 * w + tq;
  const int lr1 = lr0 + 8;
  const float qmul = QSCALE * LOG2E;

  __syncthreads();
  char* stg = (char*)sm;

  if (sec < 2) {
    const float scale = (sec == 0) ? qmul : 1.0f;
#pragma unroll
    for (int nt = 0; nt < 8; ++nt) {
      int c0 = nt * 8 + 2 * tr;
      int pp = packc16(c0) * 2;
      float b0 = bb2[nt].x, b1 = bb2[nt].y;
      __nv_bfloat162 v0, v1;
      v0.x = __float2bfloat16_rn((s[nt][0] + b0) * scale);
      v0.y = __float2bfloat16_rn((s[nt][1] + b1) * scale);
      v1.x = __float2bfloat16_rn((s[nt][2] + b0) * scale);
      v1.y = __float2bfloat16_rn((s[nt][3] + b1) * scale);
      *(__nv_bfloat162*)(stg + lr0 * 144 + pp) = v0;
      *(__nv_bfloat162*)(stg + lr1 * 144 + pp) = v1;
    }
  } else {
    const bool z0 = (row0 + lr0) < npadd;
    const bool z1 = (row0 + lr1) < npadd;
    const int pk0 = packc16(lr0) * 2, pk1 = packc16(lr1) * 2;
#pragma unroll
    for (int nt = 0; nt < 8; ++nt) {
      int c0 = nt * 8 + 2 * tr, c1 = c0 + 1;
      float b0 = bb2[nt].x, b1 = bb2[nt].y;
      *(__half*)(stg + c0 * 272 + pk0) = __float2half_rn(z0 ? 0.0f : s[nt][0] + b0);
      *(__half*)(stg + c1 * 272 + pk0) = __float2half_rn(z0 ? 0.0f : s[nt][1] + b1);
      *(__half*)(stg + c0 * 272 + pk1) = __float2half_rn(z1 ? 0.0f : s[nt][2] + b0);
      *(__half*)(stg + c1 * 272 + pk1) = __float2half_rn(z1 ? 0.0f : s[nt][3] + b1);
    }
  }
  __syncthreads();

  if (sec < 2) {
    char* gd = (char*)((sec == 0) ? g_Qh : g_Kh);
#pragma unroll
    for (int it = 0; it < 4; ++it) {
      int idx = tid + it * 256;
      int r = idx >> 3, seg = idx & 7;
      *(float4*)(gd + (size_t)(row0 + r) * 256 + wcb * 2 + seg * 16) =
          *(const float4*)(stg + r * 144 + seg * 16);
    }
  } else {
    char* gd = (char*)g_Vh;
#pragma unroll
    for (int it = 0; it < 4; ++it) {
      int idx = tid + it * 256;
      int d = idx >> 4, seg = idx & 15;
      *(float4*)(gd + ((size_t)(wcb + d) * T + row0) * 2 + seg * 16) =
          *(const float4*)(stg + d * 272 + seg * 16);
    }
  }
}

// ---------------------------------------------------------------------------
// Kernel 2: flash attention — exact round-14 configuration (best measured):
// NKT chunks, descending launch order, split prologue groups.
// ---------------------------------------------------------------------------
__global__ void __launch_bounds__(256, 2) attn_kernel(const int* __restrict__ npadd_p,
                                                      float* __restrict__ out) {
  extern __shared__ char smc[];

  const int tid = threadIdx.x;
  const int lane = tid & 31;
  const int w = tid >> 5;
  const int tq = lane >> 2;
  const int tr = lane & 3;

  // bid -> (qt, ch): group g = qt>>3 has 8 qtiles x (g+1) chunks.
  const int bid = (NCTA_ATTN - 1) - blockIdx.x;   // big qt first
  int g = 0;
  while (4 * (g + 1) * (g + 2) <= bid) ++g;
  const int idx0 = bid - 4 * g * (g + 1);
  const int qi = idx0 / (g + 1);
  const int ch = idx0 - qi * (g + 1);
  const int qt = 8 * g + qi;
  const int nch = g + 1;

  const int kcount = 2 * (qt + 1);
  const int k0 = ch * NKT;
  const int k1 = (k0 + NKT < kcount) ? (k0 + NKT) : kcount;
  const int npadd = *npadd_p;
  const int qrow0 = qt * BM;

  const uint32_t sb = smem_u32(smc);

  // ---- prologue: group 1 = Q + K(0); group 2 = V(0) ----
  {
    const char* qsrc = (const char*)g_Qh + (size_t)qrow0 * (NF * 2);
#pragma unroll
    for (int it = 0; it < 8; ++it) {
      int idx = tid + it * 256;
      int r = idx >> 4, seg = idx & 15;
      cp16(sb + QS_OFF + r * QSTB + seg * 16, qsrc + r * (NF * 2) + seg * 16);
    }
    const int kbase = k0 * BN;
    const char* ksrc = (const char*)g_Kh + (size_t)kbase * (NF * 2);
#pragma unroll
    for (int it = 0; it < 4; ++it) {
      int idx = tid + it * 256;
      int r = idx >> 4, seg = idx & 15;
      cp16(sb + r * KSTB + seg * 16, ksrc + r * (NF * 2) + seg * 16);
    }
    CP_COMMIT();                           // group: Q + K(0)
    const char* vsrc = (const char*)g_Vh + (size_t)kbase * 2;
#pragma unroll
    for (int it = 0; it < 4; ++it) {
      int idx = tid + it * 256;
      int r = idx >> 3, seg = idx & 7;
      cp16(sb + K_TILE + r * VSTB + seg * 16, vsrc + (size_t)r * (T * 2) + seg * 16);
    }
    CP_COMMIT();                           // group: V(0)
    CP_WAIT1();                            // Q + K(0) complete; V(0) in flight
  }
  __syncthreads();

  const int r0g = qrow0 + 16 * w + tq;
  const int r1g = r0g + 8;
  float o[16][4];
#pragma unroll
  for (int n = 0; n < 16; ++n)
#pragma unroll
    for (int i = 0; i < 4; ++i) o[n][i] = 0.0f;
  float oS[4] = {0.0f, 0.0f, 0.0f, 0.0f};   // row sums via ones-mma
  const uint32_t ones2[2] = {0x3C003C00u, 0x3C003C00u};

  char* pw = smc + PS_OFF + w * 16 * PSTB;
  const char* q0p = smc + QS_OFF + (16 * w + tq) * QSTB + tr * 8;
  const char* Ks = smc;
  const char* Vs = smc + K_TILE;

  for (int kt = k0; kt < k1; ++kt) {
    const int kbase = kt * BN;

    // ---- S = Q @ K^T ----
    float s[8][4];
#pragma unroll
    for (int n = 0; n < 8; ++n)
#pragma unroll
      for (int i = 0; i < 4; ++i) s[n][i] = 0.0f;

#pragma unroll
    for (int kk = 0; kk < 8; ++kk) {
      uint2 l0 = *(const uint2*)(q0p + kk * 32);
      uint2 l1 = *(const uint2*)(q0p + 8 * QSTB + kk * 32);
      uint32_t qa[4] = {l0.x, l1.x, l0.y, l1.y};
#pragma unroll
      for (int nt = 0; nt < 8; ++nt) {
        uint2 bb = *(const uint2*)(Ks + (nt * 8 + tq) * KSTB + kk * 32 + tr * 8);
        mma_bf16(s[nt], qa, (const uint32_t*)&bb);
      }
    }
    __syncthreads();                       // all warps done reading Ks

    // ---- prefetch K(t+1) ----
    if (kt + 1 < k1) {
      const char* ksrc = (const char*)g_Kh + (size_t)(kt + 1) * BN * (NF * 2);
#pragma unroll
      for (int it = 0; it < 4; ++it) {
        int idx = tid + it * 256;
        int r = idx >> 4, seg = idx & 15;
        cp16(sb + r * KSTB + seg * 16, ksrc + r * (NF * 2) + seg * 16);
      }
    }
    CP_COMMIT();                           // K group

    // ---- mask ----
    const bool needmask = (kbase + BN > qrow0) || (kbase < npadd) || (qrow0 < npadd);
    if (needmask) {
#pragma unroll
      for (int nt = 0; nt < 8; ++nt) {
        int j0 = kbase + nt * 8 + 2 * tr;
        int j1 = j0 + 1;
        if (j0 > r0g || j0 < npadd || r0g < npadd) s[nt][0] = neg_inf();
        if (j1 > r0g || j1 < npadd || r0g < npadd) s[nt][1] = neg_inf();
        if (j0 > r1g || j0 < npadd || r1g < npadd) s[nt][2] = neg_inf();
        if (j1 > r1g || j1 < npadd || r1g < npadd) s[nt][3] = neg_inf();
      }
    }

    // ---- P = exp2(S) in fp16x2 (no max subtraction needed) ----
#pragma unroll
    for (int nth = 0; nth < 4; ++nth) {
      int nt = 2 * nth;
      uint2 st0, st1;
      st0.x = exp2_f16x2(s[nt][0], s[nt][1]);
      st0.y = exp2_f16x2(s[nt + 1][0], s[nt + 1][1]);
      st1.x = exp2_f16x2(s[nt][2], s[nt][3]);
      st1.y = exp2_f16x2(s[nt + 1][2], s[nt + 1][3]);
      int off = nth * 32 + tr * 8;
      *(uint2*)(pw + tq * PSTB + off) = st0;
      *(uint2*)(pw + (tq + 8) * PSTB + off) = st1;
    }

    CP_WAIT1();                            // V(t) complete (older than K(t+1))
    __syncthreads();                       // V + P visible

    // ---- O += P @ V ; row sums += P @ ones ----
#pragma unroll
    for (int ktk = 0; ktk < 4; ++ktk) {
      uint2 p0 = *(const uint2*)(pw + tq * PSTB + ktk * 32 + tr * 8);
      uint2 p1 = *(const uint2*)(pw + (tq + 8) * PSTB + ktk * 32 + tr * 8);
      uint32_t pa[4] = {p0.x, p1.x, p0.y, p1.y};
#pragma unroll
      for (int nt2 = 0; nt2 < 16; ++nt2) {
        uint2 bb = *(const uint2*)(Vs + (nt2 * 8 + tq) * VSTB + ktk * 32 + tr * 8);
        mma_f16(o[nt2], pa, (const uint32_t*)&bb);
      }
      mma_f16(oS, pa, ones2);              // l accumulation on the tensor pipe
    }
    __syncthreads();                       // all warps done reading Vs

    // ---- prefetch V(t+1) ----
    if (kt + 1 < k1) {
      const char* vsrc = (const char*)g_Vh + (size_t)(kt + 1) * BN * 2;
#pragma unroll
      for (int it = 0; it < 4; ++it) {
        int idx = tid + it * 256;
        int r = idx >> 3, seg = idx & 7;
        cp16(sb + K_TILE + r * VSTB + seg * 16, vsrc + (size_t)r * (T * 2) + seg * 16);
      }
    }
    CP_COMMIT();                           // V group
    CP_WAIT1();                            // K(t+1) complete
    __syncthreads();                       // K visible
  }

  const float l0s = oS[0];
  const float l1s = oS[2];

  // ---- epilogue ----
  if (nch == 1) {
    float rn0 = (l0s > 0.0f) ? (1.0f / l0s) : 0.0f;
    float rn1 = (l1s > 0.0f) ? (1.0f / l1s) : 0.0f;
    float* ob0 = &out[(size_t)r0g * NF];
    float* ob1 = &out[(size_t)r1g * NF];
#pragma unroll
    for (int nt2 = 0; nt2 < 16; ++nt2) {
      int c = nt2 * 8 + 2 * tr;
      *(float2*)&ob0[c] = make_float2(o[nt2][0] * rn0, o[nt2][1] * rn0);
      *(float2*)&ob1[c] = make_float2(o[nt2][2] * rn1, o[nt2][3] * rn1);
    }
  } else {
    float* ob0 = &g_O[((size_t)ch * T + r0g) * NF];
    float* ob1 = &g_O[((size_t)ch * T + r1g) * NF];
#pragma unroll
    for (int nt2 = 0; nt2 < 16; ++nt2) {
      int c = nt2 * 8 + 2 * tr;
      *(float2*)&ob0[c] = make_float2(o[nt2][0], o[nt2][1]);
      *(float2*)&ob1[c] = make_float2(o[nt2][2], o[nt2][3]);
    }
    if (tr == 0) {
      g_L[ch * T + r0g] = l0s; g_L[ch * T + r1g] = l1s;
    }
  }
}

// ---------------------------------------------------------------------------
// Kernel 3: combine split partials — float4 per thread (4 cols), rows >= 1024.
// Per-column accumulation order and num/den division identical to before.
// ---------------------------------------------------------------------------
__global__ void __launch_bounds__(256) combine_kernel(float* __restrict__ out) {
  const int idx = blockIdx.x * 256 + threadIdx.x;   // thread -> (row, 4 cols)
  const int t = 1024 + (idx >> 5);                  // 32 threads per row
  const int c4 = (idx & 31) * 4;
  const int qt = t >> 7;
  const int nch = (qt >> 3) + 1;

  float den = 0.0f;
  float4 num = make_float4(0.0f, 0.0f, 0.0f, 0.0f);
  for (int s = 0; s < nch; ++s) {
    den += g_L[s * T + t];
    float4 v = *(const float4*)&g_O[((size_t)s * T + t) * NF + c4];
    num.x += v.x; num.y += v.y; num.z += v.z; num.w += v.w;
  }
  float4 o4;
  if (den > 0.0f) {
    o4.x = num.x / den; o4.y = num.y / den;
    o4.z = num.z / den; o4.w = num.w / den;
  } else {
    o4 = make_float4(0.0f, 0.0f, 0.0f, 0.0f);
  }
  *(float4*)&out[(size_t)t * NF + c4] = o4;
}

// ---------------------------------------------------------------------------
extern "C" void kernel_launch(void* const* d_in, const int* in_sizes, int n_in,
                              void* d_out, int out_size) {
  const float* x = (const float*)d_in[0];
  const float* W = (const float*)d_in[1];
  const float* b = (const float*)d_in[2];
  const int* npadd = (const int*)d_in[3];
  float* out = (float*)d_out;

  constexpr int PROJ_SMEM = (128 * XST + 64 * WST2) * (int)sizeof(float);  // 100KB
  cudaFuncSetAttribute(proj_kernel, cudaFuncAttributeMaxDynamicSharedMemorySize, PROJ_SMEM);
  cudaFuncSetAttribute(attn_kernel, cudaFuncAttributeMaxDynamicSharedMemorySize, ATTN_SMEM);

  proj_kernel<<<dim3(64, 6), 256, PROJ_SMEM>>>(x, W, b, npadd);
  attn_kernel<<<NCTA_ATTN, 256, ATTN_SMEM>>>(npadd, out);
  combine_kernel<<<(T - 1024) * 32 / 256, 256>>>(out);
}